// round 2
// baseline (speedup 1.0000x reference)
#include <cuda_runtime.h>
#include <cuda_bf16.h>
#include <math.h>
#include <stdint.h>

// Problem sizes (fixed by the dataset)
#define Bq  32
#define Sq  2048
#define HEq 1024
#define HDq 1024

// ---------------- persistent device scratch (no allocations allowed) -------
__device__ float          g_dec_proj[Bq * HDq];      // W_dec @ dec_hidden
__device__ __nv_bfloat16  g_Whi[HDq * HEq];          // bf16 split of W_enc (hi)
__device__ __nv_bfloat16  g_Wlo[HDq * HEq];          // bf16 split of W_enc (lo)
__device__ float          g_scores[Bq * Sq];         // pre-softmax scores
__device__ int            g_idx[Bq * Sq];            // compacted unmasked s per b
__device__ int            g_cnt[Bq];                 // count of unmasked per b
__device__ int            g_mask_stride;             // 1 (bool bytes) or 4 (int32)

// ---------------- helpers --------------------------------------------------
__device__ __forceinline__ void mma16816(float* d, const unsigned* a, const unsigned* b) {
    asm volatile(
        "mma.sync.aligned.m16n8k16.row.col.f32.bf16.bf16.f32 "
        "{%0,%1,%2,%3}, {%4,%5,%6,%7}, {%8,%9}, {%0,%1,%2,%3};\n"
        : "+f"(d[0]), "+f"(d[1]), "+f"(d[2]), "+f"(d[3])
        : "r"(a[0]), "r"(a[1]), "r"(a[2]), "r"(a[3]), "r"(b[0]), "r"(b[1]));
}

__device__ __forceinline__ void split_store(float4 v, __nv_bfloat16* hd, __nv_bfloat16* ld) {
    __nv_bfloat16 h[4], l[4];
    h[0] = __float2bfloat16(v.x); l[0] = __float2bfloat16(v.x - __bfloat162float(h[0]));
    h[1] = __float2bfloat16(v.y); l[1] = __float2bfloat16(v.y - __bfloat162float(h[1]));
    h[2] = __float2bfloat16(v.z); l[2] = __float2bfloat16(v.z - __bfloat162float(h[2]));
    h[3] = __float2bfloat16(v.w); l[3] = __float2bfloat16(v.w - __bfloat162float(h[3]));
    *(uint2*)hd = *(uint2*)h;
    *(uint2*)ld = *(uint2*)l;
}

// ---------------- K_detect: mask element byte-width ------------------------
// bool arrays: ~50% nonzero bytes everywhere. int32 arrays: bytes at off%4!=0
// are all zero (little-endian 0/1 values). Scan first 4KB.
__global__ void maskdetect_kernel(const uint8_t* __restrict__ mask) {
    __shared__ int any;
    if (threadIdx.x == 0) any = 0;
    __syncthreads();
    int local = 0;
    for (int i = threadIdx.x; i < 4096; i += 256)
        if ((i & 3) && mask[i]) local = 1;
    if (local) atomicOr(&any, 1);
    __syncthreads();
    if (threadIdx.x == 0) g_mask_stride = any ? 1 : 4;
}

// ---------------- K0: split W_enc into bf16 hi/lo --------------------------
__global__ void splitw_kernel(const float* __restrict__ W) {
    int idx = blockIdx.x * blockDim.x + threadIdx.x;
    if (idx >= HDq * HEq) return;
    int d = idx >> 10, e = idx & 1023;
    float w = W[(size_t)d * (HEq + HDq) + e];
    __nv_bfloat16 h = __float2bfloat16(w);
    g_Whi[idx] = h;
    g_Wlo[idx] = __float2bfloat16(w - __bfloat162float(h));
}

// ---------------- K1: dec_proj[b][d] = sum_e dec[b][e] * W[d][HE+e] --------
__global__ void decproj_kernel(const float* __restrict__ dec, const float* __restrict__ W) {
    int warp = (blockIdx.x * blockDim.x + threadIdx.x) >> 5;
    int lane = threadIdx.x & 31;
    if (warp >= Bq * HDq) return;
    int b = warp >> 10, d = warp & 1023;
    const float4* dr = (const float4*)(dec + (size_t)b * HDq);
    const float4* wr = (const float4*)(W + (size_t)d * (HEq + HDq) + HEq);
    float s = 0.f;
    #pragma unroll
    for (int j = lane; j < HDq / 4; j += 32) {
        float4 x = dr[j], w = wr[j];
        s += x.x * w.x + x.y * w.y + x.z * w.z + x.w * w.w;
    }
    #pragma unroll
    for (int o = 16; o > 0; o >>= 1) s += __shfl_xor_sync(0xffffffffu, s, o);
    if (lane == 0) g_dec_proj[warp] = s;
}

// ---------------- Kc: compact unmasked s indices per b ---------------------
__global__ void compact_kernel(const uint8_t* __restrict__ mask) {
    int b = blockIdx.x, t = threadIdx.x;
    int stride = g_mask_stride;
    for (int s = t; s < Sq; s += 256) {
        if (mask[(size_t)(b * Sq + s) * stride] == 0) {
            int p = atomicAdd(&g_cnt[b], 1);
            g_idx[b * Sq + p] = s;
        }
    }
}

// ---------------- K2: main GEMM + tanh + V-dot (scores) --------------------
// C[i][d] = sum_e enc[i][e]*W_enc[d][e]; score[i] += sum_d tanh(C+dp)*V[d]
// 3-term bf16-split via mma.sync m16n8k16. Block tile 128x64x32, 8 warps.
#define BM 128
#define BN 64
#define BK 32
#define PK 40                 // padded smem row stride (bf16 elems): conflict-free
#define A_BUF (BM * PK)
#define B_BUF (BN * PK)
#define SMEM_K2_BYTES ((2 * A_BUF * 2 + 2 * B_BUF * 2) * (int)sizeof(__nv_bfloat16) + 2 * BN * (int)sizeof(float))

__global__ void __launch_bounds__(256) attn_gemm_kernel(
    const float* __restrict__ enc, const float* __restrict__ Vv)
{
    int b    = blockIdx.y >> 4;
    int tile = blockIdx.y & 15;
    int cnt  = g_cnt[b];
    if (tile * BM >= cnt) return;            // whole tile masked out -> skip
    int nbase = blockIdx.x * BN;

    extern __shared__ char smem_raw[];
    __nv_bfloat16* sAhi = (__nv_bfloat16*)smem_raw;
    __nv_bfloat16* sAlo = sAhi + 2 * A_BUF;
    __nv_bfloat16* sBhi = sAlo + 2 * A_BUF;
    __nv_bfloat16* sBlo = sBhi + 2 * B_BUF;
    float* dpV = (float*)(sBlo + 2 * B_BUF);     // [0,64)=dec_proj, [64,128)=V

    int t = threadIdx.x;
    int lane = t & 31, warp = t >> 5;
    int wm = warp & 3, wn = warp >> 2;           // 4 x 2 warp grid (M x N)
    int g = lane >> 2, t4 = lane & 3;

    // Per-thread A row pointers (gathered rows; fixed over the K loop)
    const float* Aptr[4];
    int stsA[4];
    #pragma unroll
    for (int i = 0; i < 4; i++) {
        int linear = i * 256 + t;
        int r = linear >> 3, c4 = linear & 7;
        int rb = tile * BM + r;
        int s = g_idx[b * Sq + ((rb < cnt) ? rb : (cnt - 1))];
        Aptr[i] = enc + (size_t)(b * Sq + s) * HEq + c4 * 4;
        stsA[i] = r * PK + c4 * 4;
    }
    int rB = t >> 2, cB = t & 3;
    const __nv_bfloat16* BhiPtr = g_Whi + (size_t)(nbase + rB) * HEq + cB * 8;
    const __nv_bfloat16* BloPtr = g_Wlo + (size_t)(nbase + rB) * HEq + cB * 8;
    int stsB = rB * PK + cB * 8;

    float4 aS[4]; uint4 bhS, blS;

    // ---- prologue: load k-chunk 0, stage to smem buf 0 ----
    #pragma unroll
    for (int i = 0; i < 4; i++) aS[i] = *(const float4*)(Aptr[i]);
    bhS = *(const uint4*)(BhiPtr);
    blS = *(const uint4*)(BloPtr);
    #pragma unroll
    for (int i = 0; i < 4; i++) split_store(aS[i], sAhi + stsA[i], sAlo + stsA[i]);
    *(uint4*)(sBhi + stsB) = bhS;
    *(uint4*)(sBlo + stsB) = blS;
    if (t < BN)            dpV[t] = g_dec_proj[b * HDq + nbase + t];
    else if (t < 2 * BN)   dpV[t] = Vv[nbase + t - BN];
    __syncthreads();

    float acc[2][4][4];
    #pragma unroll
    for (int mi = 0; mi < 2; mi++)
        #pragma unroll
        for (int ni = 0; ni < 4; ni++)
            #pragma unroll
            for (int c = 0; c < 4; c++) acc[mi][ni][c] = 0.f;

    const int NK = HEq / BK;                      // 32 k-iterations
    for (int kt = 0; kt < NK; ++kt) {
        int buf = kt & 1;
        if (kt + 1 < NK) {                        // prefetch next chunk to regs
            #pragma unroll
            for (int i = 0; i < 4; i++) aS[i] = *(const float4*)(Aptr[i] + (kt + 1) * BK);
            bhS = *(const uint4*)(BhiPtr + (kt + 1) * BK);
            blS = *(const uint4*)(BloPtr + (kt + 1) * BK);
        }
        #pragma unroll
        for (int k16 = 0; k16 < BK; k16 += 16) {
            unsigned ah[2][4], al[2][4], bh[4][2], bl[4][2];
            #pragma unroll
            for (int mi = 0; mi < 2; mi++) {
                int off = buf * A_BUF + (wm * 32 + mi * 16 + g) * PK + k16 + t4 * 2;
                ah[mi][0] = *(const unsigned*)(sAhi + off);
                ah[mi][1] = *(const unsigned*)(sAhi + off + 8 * PK);
                ah[mi][2] = *(const unsigned*)(sAhi + off + 8);
                ah[mi][3] = *(const unsigned*)(sAhi + off + 8 * PK + 8);
                al[mi][0] = *(const unsigned*)(sAlo + off);
                al[mi][1] = *(const unsigned*)(sAlo + off + 8 * PK);
                al[mi][2] = *(const unsigned*)(sAlo + off + 8);
                al[mi][3] = *(const unsigned*)(sAlo + off + 8 * PK + 8);
            }
            #pragma unroll
            for (int ni = 0; ni < 4; ni++) {
                int off = buf * B_BUF + (wn * 32 + ni * 8 + g) * PK + k16 + t4 * 2;
                bh[ni][0] = *(const unsigned*)(sBhi + off);
                bh[ni][1] = *(const unsigned*)(sBhi + off + 8);
                bl[ni][0] = *(const unsigned*)(sBlo + off);
                bl[ni][1] = *(const unsigned*)(sBlo + off + 8);
            }
            #pragma unroll
            for (int mi = 0; mi < 2; mi++)
                #pragma unroll
                for (int ni = 0; ni < 4; ni++) {
                    mma16816(acc[mi][ni], ah[mi], bh[ni]);  // hi*hi
                    mma16816(acc[mi][ni], ah[mi], bl[ni]);  // hi*lo
                    mma16816(acc[mi][ni], al[mi], bh[ni]);  // lo*hi
                }
        }
        if (kt + 1 < NK) {
            __syncthreads();
            int nb = (kt + 1) & 1;
            #pragma unroll
            for (int i = 0; i < 4; i++)
                split_store(aS[i], sAhi + nb * A_BUF + stsA[i], sAlo + nb * A_BUF + stsA[i]);
            *(uint4*)(sBhi + nb * B_BUF + stsB) = bhS;
            *(uint4*)(sBlo + nb * B_BUF + stsB) = blS;
            __syncthreads();
        }
    }

    // ---- fused epilogue: tanh(+dec_proj), dot with V, atomic to scores ----
    const float* dp = dpV;
    const float* Vs = dpV + BN;
    #pragma unroll
    for (int mi = 0; mi < 2; mi++) {
        #pragma unroll
        for (int half = 0; half < 2; half++) {
            float p = 0.f;
            #pragma unroll
            for (int ni = 0; ni < 4; ni++) {
                int c0 = wn * 32 + ni * 8 + t4 * 2;
                p += tanhf(acc[mi][ni][half * 2 + 0] + dp[c0])     * Vs[c0];
                p += tanhf(acc[mi][ni][half * 2 + 1] + dp[c0 + 1]) * Vs[c0 + 1];
            }
            p += __shfl_xor_sync(0xffffffffu, p, 1);
            p += __shfl_xor_sync(0xffffffffu, p, 2);
            if (t4 == 0) {
                int rl = wm * 32 + mi * 16 + half * 8 + g;
                int rb = tile * BM + rl;
                if (rb < cnt) {
                    int s = g_idx[b * Sq + rb];
                    atomicAdd(&g_scores[b * Sq + s], p);
                }
            }
        }
    }
}

// ---------------- K3: masked softmax over S, write attn --------------------
__global__ void softmax_kernel(const uint8_t* __restrict__ mask, float* __restrict__ attn) {
    int b = blockIdx.x, t = threadIdx.x;
    int stride = g_mask_stride;
    __shared__ float red[256];
    const uint8_t* mb = mask;
    const float* sb = g_scores + b * Sq;

    float mx = -INFINITY;
    for (int s = t; s < Sq; s += 256)
        if (mb[(size_t)(b * Sq + s) * stride] == 0) mx = fmaxf(mx, sb[s]);
    red[t] = mx; __syncthreads();
    for (int o = 128; o > 0; o >>= 1) { if (t < o) red[t] = fmaxf(red[t], red[t + o]); __syncthreads(); }
    float M = red[0]; __syncthreads();

    float sum = 0.f;
    for (int s = t; s < Sq; s += 256)
        if (mb[(size_t)(b * Sq + s) * stride] == 0) sum += expf(sb[s] - M);
    red[t] = sum; __syncthreads();
    for (int o = 128; o > 0; o >>= 1) { if (t < o) red[t] += red[t + o]; __syncthreads(); }
    float inv = 1.0f / red[0];

    for (int s = t; s < Sq; s += 256) {
        bool m = mb[(size_t)(b * Sq + s) * stride] != 0;
        attn[b * Sq + s] = m ? 0.0f : expf(sb[s] - M) * inv;
    }
}

// ---------------- K4: ctx[b][e] = sum_s attn[b][s] * enc[b][s][e] ----------
__global__ void ctx_kernel(const float* __restrict__ enc,
                           const float* __restrict__ attn,
                           float* __restrict__ ctx) {
    int b = blockIdx.x;
    int chunk = blockIdx.y;                  // 16 chunks of 128 s each
    int t = threadIdx.x;                     // 256 threads x float4 = HE
    float4 acc = make_float4(0.f, 0.f, 0.f, 0.f);
    const float* encb = enc + (size_t)b * Sq * HEq;
    int s0 = chunk * 128;
    for (int s = s0; s < s0 + 128; ++s) {
        float a = attn[b * Sq + s];
        if (a != 0.f) {                      // uniform branch: skip masked rows
            float4 v = *(const float4*)(encb + (size_t)s * HEq + t * 4);
            acc.x += a * v.x; acc.y += a * v.y; acc.z += a * v.z; acc.w += a * v.w;
        }
    }
    float* dst = ctx + (size_t)b * HEq + t * 4;
    atomicAdd(dst + 0, acc.x);
    atomicAdd(dst + 1, acc.y);
    atomicAdd(dst + 2, acc.z);
    atomicAdd(dst + 3, acc.w);
}

// ---------------- launch ---------------------------------------------------
extern "C" void kernel_launch(void* const* d_in, const int* in_sizes, int n_in,
                              void* d_out, int out_size) {
    const float*   enc  = (const float*)d_in[0];   // (32, 2048, 1024) f32
    const float*   dec  = (const float*)d_in[1];   // (32, 1024) f32
    const uint8_t* mask = (const uint8_t*)d_in[2]; // (32, 2048) bool (stride-detected)
    const float*   W    = (const float*)d_in[3];   // (1024, 2048) f32
    const float*   V    = (const float*)d_in[4];   // (1, 1024) f32

    float* out  = (float*)d_out;
    float* ctx  = out;                 // first 32*1024 floats
    float* attn = out + Bq * HEq;      // next 32*2048 floats

    void* p_scores; cudaGetSymbolAddress(&p_scores, g_scores);
    void* p_cnt;    cudaGetSymbolAddress(&p_cnt, g_cnt);
    cudaMemsetAsync(p_scores, 0, sizeof(float) * Bq * Sq);
    cudaMemsetAsync(p_cnt,    0, sizeof(int) * Bq);
    cudaMemsetAsync(ctx,      0, sizeof(float) * Bq * HEq);

    maskdetect_kernel<<<1, 256>>>(mask);
    splitw_kernel<<<(HDq * HEq + 255) / 256, 256>>>(W);
    decproj_kernel<<<(Bq * HDq * 32 + 255) / 256, 256>>>(dec, W);
    compact_kernel<<<Bq, 256>>>(mask);

    cudaFuncSetAttribute(attn_gemm_kernel,
                         cudaFuncAttributeMaxDynamicSharedMemorySize, SMEM_K2_BYTES);
    dim3 grid2(HDq / BN, Bq * (Sq / BM));   // (16, 512)
    attn_gemm_kernel<<<grid2, 256, SMEM_K2_BYTES>>>(enc, V);

    softmax_kernel<<<Bq, 256>>>(mask, attn);
    ctx_kernel<<<dim3(Bq, 16), 256>>>(enc, attn, ctx);
}

// round 5
// speedup vs baseline: 1.1576x; 1.1576x over previous
#include <cuda_runtime.h>
#include <cuda_bf16.h>
#include <math.h>
#include <stdint.h>

// Problem sizes (fixed by the dataset)
#define Bq  32
#define Sq  2048
#define HEq 1024
#define HDq 1024

// ---------------- persistent device scratch (no allocations allowed) -------
__device__ float          g_dec_proj[Bq * HDq];        // W_dec @ dec_hidden
__device__ __nv_bfloat16  g_Whi[HDq * HEq];            // bf16 split of W_enc (hi)
__device__ __nv_bfloat16  g_Wlo[HDq * HEq];            // bf16 split of W_enc (lo)
__device__ __nv_bfloat16  g_Ahi[Bq * Sq * HEq];        // compacted enc rows, hi
__device__ __nv_bfloat16  g_Alo[Bq * Sq * HEq];        // compacted enc rows, lo
__device__ float          g_scores[Bq * Sq];           // scores in SLOT space
__device__ int            g_idx[Bq * Sq];              // slot -> s
__device__ int            g_cnt[Bq];                   // unmasked count per b
__device__ int            g_mask_stride;               // 1 (bool) or 4 (int32)

// ---------------- helpers --------------------------------------------------
__device__ __forceinline__ uint32_t smem_u32(const void* p) {
    uint32_t a;
    asm("{ .reg .u64 t; cvta.to.shared.u64 t, %1; cvt.u32.u64 %0, t; }" : "=r"(a) : "l"(p));
    return a;
}
__device__ __forceinline__ uint32_t sw128(uint32_t o) { return o ^ ((o >> 3) & 0x70); }

__device__ __forceinline__ void mma16816(float* d, const unsigned* a, unsigned b0, unsigned b1) {
    asm volatile(
        "mma.sync.aligned.m16n8k16.row.col.f32.bf16.bf16.f32 "
        "{%0,%1,%2,%3}, {%4,%5,%6,%7}, {%8,%9}, {%0,%1,%2,%3};\n"
        : "+f"(d[0]), "+f"(d[1]), "+f"(d[2]), "+f"(d[3])
        : "r"(a[0]), "r"(a[1]), "r"(a[2]), "r"(a[3]), "r"(b0), "r"(b1));
}
__device__ __forceinline__ void ldsm4(unsigned* r, uint32_t addr) {
    asm volatile("ldmatrix.sync.aligned.m8n8.x4.shared.b16 {%0,%1,%2,%3}, [%4];"
                 : "=r"(r[0]), "=r"(r[1]), "=r"(r[2]), "=r"(r[3]) : "r"(addr));
}
#define CP16(dst, src)  asm volatile("cp.async.cg.shared.global [%0], [%1], 16;" :: "r"(dst), "l"(src))
#define CP_COMMIT()     asm volatile("cp.async.commit_group;")
#define CP_WAIT1()      asm volatile("cp.async.wait_group 1;")
#define CP_WAIT0()      asm volatile("cp.async.wait_group 0;")

// ---------------- K_detect: mask element byte-width ------------------------
__global__ void maskdetect_kernel(const uint8_t* __restrict__ mask) {
    __shared__ int any;
    if (threadIdx.x == 0) any = 0;
    __syncthreads();
    int local = 0;
    for (int i = threadIdx.x; i < 4096; i += 256)
        if ((i & 3) && mask[i]) local = 1;
    if (local) atomicOr(&any, 1);
    __syncthreads();
    if (threadIdx.x == 0) g_mask_stride = any ? 1 : 4;
}

// ---------------- Kc: compact unmasked s indices per b ---------------------
__global__ void compact_kernel(const uint8_t* __restrict__ mask) {
    int b = blockIdx.x, t = threadIdx.x;
    int stride = g_mask_stride;
    for (int s = t; s < Sq; s += 256) {
        if (mask[(size_t)(b * Sq + s) * stride] == 0) {
            int p = atomicAdd(&g_cnt[b], 1);
            g_idx[b * Sq + p] = s;
        }
    }
}

// ---------------- K0: split W_enc into bf16 hi/lo --------------------------
__global__ void splitw_kernel(const float* __restrict__ W) {
    int idx = blockIdx.x * blockDim.x + threadIdx.x;
    if (idx >= HDq * HEq) return;
    int d = idx >> 10, e = idx & 1023;
    float w = W[(size_t)d * (HEq + HDq) + e];
    __nv_bfloat16 h = __float2bfloat16(w);
    g_Whi[idx] = h;
    g_Wlo[idx] = __float2bfloat16(w - __bfloat162float(h));
}

// ---------------- K0b: gather + split enc into compacted bf16 hi/lo --------
// grid (Bq, 16) x 256 threads; block handles 128 slots x 1024 cols.
__global__ void convertA_kernel(const float* __restrict__ enc) {
    int b = blockIdx.x, tile = blockIdx.y, t = threadIdx.x;
    int cnt = g_cnt[b];
    int pad = (cnt + 127) & ~127;
    int slot0 = tile * 128;
    if (slot0 >= pad) return;
    for (int i = 0; i < 128; i++) {
        int slot = slot0 + i;
        size_t dsto = ((size_t)(b * Sq + slot)) * HEq + t * 4;
        if (slot < cnt) {
            int s = g_idx[b * Sq + slot];
            float4 v = *(const float4*)(enc + ((size_t)(b * Sq + s)) * HEq + t * 4);
            __nv_bfloat16 h[4], l[4];
            h[0] = __float2bfloat16(v.x); l[0] = __float2bfloat16(v.x - __bfloat162float(h[0]));
            h[1] = __float2bfloat16(v.y); l[1] = __float2bfloat16(v.y - __bfloat162float(h[1]));
            h[2] = __float2bfloat16(v.z); l[2] = __float2bfloat16(v.z - __bfloat162float(h[2]));
            h[3] = __float2bfloat16(v.w); l[3] = __float2bfloat16(v.w - __bfloat162float(h[3]));
            *(uint2*)(g_Ahi + dsto) = *(uint2*)h;
            *(uint2*)(g_Alo + dsto) = *(uint2*)l;
        } else {
            uint2 z = make_uint2(0u, 0u);
            *(uint2*)(g_Ahi + dsto) = z;
            *(uint2*)(g_Alo + dsto) = z;
        }
    }
}

// ---------------- K1: dec_proj[b][d] = sum_e dec[b][e] * W[d][HE+e] --------
__global__ void decproj_kernel(const float* __restrict__ dec, const float* __restrict__ W) {
    int warp = (blockIdx.x * blockDim.x + threadIdx.x) >> 5;
    int lane = threadIdx.x & 31;
    if (warp >= Bq * HDq) return;
    int b = warp >> 10, d = warp & 1023;
    const float4* dr = (const float4*)(dec + (size_t)b * HDq);
    const float4* wr = (const float4*)(W + (size_t)d * (HEq + HDq) + HEq);
    float s = 0.f;
    #pragma unroll
    for (int j = lane; j < HDq / 4; j += 32) {
        float4 x = dr[j], w = wr[j];
        s += x.x * w.x + x.y * w.y + x.z * w.z + x.w * w.w;
    }
    #pragma unroll
    for (int o = 16; o > 0; o >>= 1) s += __shfl_xor_sync(0xffffffffu, s, o);
    if (lane == 0) g_dec_proj[warp] = s;
}

// ---------------- K2: HMMA GEMM + tanh + V-dot -----------------------------
// CTA tile 128x128x64, 8 warps (warp tile 64x32), cp.async double buffer,
// ldmatrix fragment loads, 3-term bf16 split, scores in slot space.
#define BM 128
#define BN 128
#define BK 64
#define NKT (HEq / BK)                   // 16
#define STAGE_BYTES 65536                // Ahi16K | Alo16K | Bhi16K | Blo16K
#define OFF_AHI 0
#define OFF_ALO 16384
#define OFF_BHI 32768
#define OFF_BLO 49152
#define SMEM_DPV   0                     // 256 floats
#define SMEM_TILES 1024
#define SMEM_GEMM_BYTES (SMEM_TILES + 2 * STAGE_BYTES)   // 132096

__global__ void __launch_bounds__(256) attn_gemm_kernel(const float* __restrict__ Vv) {
    int b     = blockIdx.y >> 4;
    int mtile = blockIdx.y & 15;
    int cnt   = g_cnt[b];
    if (mtile * BM >= cnt) return;
    int nbase = blockIdx.x * BN;

    extern __shared__ char smem[];
    uint32_t sb = smem_u32(smem);
    int t = threadIdx.x;
    int lane = t & 31, warp = t >> 5;
    int wm = warp & 1, wn = warp >> 1;           // 2 x 4 warp grid

    float* dpV = (float*)(smem + SMEM_DPV);
    if (t < 128)       dpV[t]       = g_dec_proj[b * HDq + nbase + t];
    else               dpV[t]       = Vv[nbase + t - 128];   // dpV[128..255] = V

    // ---- cp.async issue: 4 chunk ids per thread per matrix ----
    const char* baseAh = (const char*)(g_Ahi + ((size_t)(b * Sq + mtile * BM)) * HEq);
    const char* baseAl = (const char*)(g_Alo + ((size_t)(b * Sq + mtile * BM)) * HEq);
    const char* baseBh = (const char*)(g_Whi + (size_t)nbase * HEq);
    const char* baseBl = (const char*)(g_Wlo + (size_t)nbase * HEq);

    auto issue_stage = [&](int kt, int bb) {
        uint32_t sbase = sb + SMEM_TILES + bb * STAGE_BYTES;
        size_t kbyte = (size_t)kt * 128;         // 64 bf16 = 128 B
        #pragma unroll
        for (int i = 0; i < 4; i++) {
            int id = i * 256 + t;
            int row = id >> 3, c = id & 7;
            uint32_t soff = sw128(row * 128 + c * 16);
            size_t goff = (size_t)row * 2048 + kbyte + c * 16;   // row stride 2KB
            CP16(sbase + OFF_AHI + soff, baseAh + goff);
            CP16(sbase + OFF_ALO + soff, baseAl + goff);
            CP16(sbase + OFF_BHI + soff, baseBh + goff);
            CP16(sbase + OFF_BLO + soff, baseBl + goff);
        }
        CP_COMMIT();
    };

    float acc[4][4][4];
    #pragma unroll
    for (int mi = 0; mi < 4; mi++)
        #pragma unroll
        for (int ni = 0; ni < 4; ni++)
            #pragma unroll
            for (int c = 0; c < 4; c++) acc[mi][ni][c] = 0.f;

    // ldmatrix per-lane addressing
    int lm   = lane >> 3;                        // matrix id 0..3
    int lrow = lane & 7;
    int aRow = wm * 64 + (lm & 1) * 8 + lrow;    // + mi*16
    int bRow = wn * 32 + (lm & 1) * 8 + lrow;    // + nf*16
    int kHalf = (lm >> 1) * 16;                  // byte offset within k16

    issue_stage(0, 0);

    #pragma unroll 1
    for (int kt = 0; kt < NKT; ++kt) {
        int bb = kt & 1;
        if (kt + 1 < NKT) { issue_stage(kt + 1, bb ^ 1); CP_WAIT1(); }
        else              { CP_WAIT0(); }
        __syncthreads();

        uint32_t sbase = sb + SMEM_TILES + bb * STAGE_BYTES;
        #pragma unroll
        for (int kk = 0; kk < 4; ++kk) {
            int kb = kk * 32 + kHalf;
            unsigned ah[4][4], al[4][4], bh[2][4], bl[2][4];
            #pragma unroll
            for (int mi = 0; mi < 4; mi++) {
                uint32_t ro = (aRow + mi * 16) * 128 + kb;
                ldsm4(ah[mi], sbase + OFF_AHI + sw128(ro));
                ldsm4(al[mi], sbase + OFF_ALO + sw128(ro));
            }
            #pragma unroll
            for (int nf = 0; nf < 2; nf++) {
                uint32_t ro = (bRow + nf * 16) * 128 + kb;
                ldsm4(bh[nf], sbase + OFF_BHI + sw128(ro));
                ldsm4(bl[nf], sbase + OFF_BLO + sw128(ro));
            }
            #pragma unroll
            for (int mi = 0; mi < 4; mi++)
                #pragma unroll
                for (int ni = 0; ni < 4; ni++) {
                    int nf = ni >> 1, nh = ni & 1;
                    mma16816(acc[mi][ni], ah[mi], bh[nf][nh], bh[nf][nh + 2]);
                    mma16816(acc[mi][ni], ah[mi], bl[nf][nh], bl[nf][nh + 2]);
                    mma16816(acc[mi][ni], al[mi], bh[nf][nh], bh[nf][nh + 2]);
                }
        }
        __syncthreads();
    }

    // ---- epilogue: tanh(+dp) . V, quad reduce, atomicAdd (slot space) ----
    const float* dp = dpV;
    const float* Vs = dpV + 128;
    #pragma unroll
    for (int mi = 0; mi < 4; mi++) {
        float p0 = 0.f, p1 = 0.f;
        #pragma unroll
        for (int ni = 0; ni < 4; ni++) {
            int c0 = wn * 32 + ni * 8 + (lane & 3) * 2;
            p0 += tanhf(acc[mi][ni][0] + dp[c0])     * Vs[c0];
            p0 += tanhf(acc[mi][ni][1] + dp[c0 + 1]) * Vs[c0 + 1];
            p1 += tanhf(acc[mi][ni][2] + dp[c0])     * Vs[c0];
            p1 += tanhf(acc[mi][ni][3] + dp[c0 + 1]) * Vs[c0 + 1];
        }
        p0 += __shfl_xor_sync(0xffffffffu, p0, 1);
        p0 += __shfl_xor_sync(0xffffffffu, p0, 2);
        p1 += __shfl_xor_sync(0xffffffffu, p1, 1);
        p1 += __shfl_xor_sync(0xffffffffu, p1, 2);
        if ((lane & 3) == 0) {
            int r0 = mtile * BM + wm * 64 + mi * 16 + (lane >> 2);
            if (r0 < cnt)     atomicAdd(&g_scores[b * Sq + r0], p0);
            if (r0 + 8 < cnt) atomicAdd(&g_scores[b * Sq + r0 + 8], p1);
        }
    }
}

// ---------------- K3: softmax over slots, scatter attn ---------------------
__global__ void softmax_kernel(float* __restrict__ attn) {
    int b = blockIdx.x, t = threadIdx.x;
    int cnt = g_cnt[b];
    __shared__ float red[256];
    const float* sbuf = g_scores + b * Sq;

    float mx = -INFINITY;
    for (int i = t; i < cnt; i += 256) mx = fmaxf(mx, sbuf[i]);
    red[t] = mx; __syncthreads();
    for (int o = 128; o > 0; o >>= 1) { if (t < o) red[t] = fmaxf(red[t], red[t + o]); __syncthreads(); }
    float M = red[0]; __syncthreads();

    float sum = 0.f;
    for (int i = t; i < cnt; i += 256) sum += expf(sbuf[i] - M);
    red[t] = sum; __syncthreads();
    for (int o = 128; o > 0; o >>= 1) { if (t < o) red[t] += red[t + o]; __syncthreads(); }
    float inv = 1.0f / red[0];

    for (int i = t; i < cnt; i += 256)
        attn[b * Sq + g_idx[b * Sq + i]] = expf(sbuf[i] - M) * inv;
}

// ---------------- K4: ctx[b][e] = sum_s attn[b][s] * enc[b][s][e] ----------
__global__ void ctx_kernel(const float* __restrict__ enc,
                           const float* __restrict__ attn,
                           float* __restrict__ ctx) {
    int b = blockIdx.x;
    int chunk = blockIdx.y;
    int t = threadIdx.x;
    float4 acc = make_float4(0.f, 0.f, 0.f, 0.f);
    const float* encb = enc + (size_t)b * Sq * HEq;
    int s0 = chunk * 128;
    for (int s = s0; s < s0 + 128; ++s) {
        float a = attn[b * Sq + s];
        if (a != 0.f) {
            float4 v = *(const float4*)(encb + (size_t)s * HEq + t * 4);
            acc.x += a * v.x; acc.y += a * v.y; acc.z += a * v.z; acc.w += a * v.w;
        }
    }
    float* dst = ctx + (size_t)b * HEq + t * 4;
    atomicAdd(dst + 0, acc.x);
    atomicAdd(dst + 1, acc.y);
    atomicAdd(dst + 2, acc.z);
    atomicAdd(dst + 3, acc.w);
}

// ---------------- launch ---------------------------------------------------
extern "C" void kernel_launch(void* const* d_in, const int* in_sizes, int n_in,
                              void* d_out, int out_size) {
    const float*   enc  = (const float*)d_in[0];
    const float*   dec  = (const float*)d_in[1];
    const uint8_t* mask = (const uint8_t*)d_in[2];
    const float*   W    = (const float*)d_in[3];
    const float*   V    = (const float*)d_in[4];

    float* out  = (float*)d_out;
    float* ctx  = out;                 // 32*1024
    float* attn = out + Bq * HEq;      // 32*2048

    void* p_scores; cudaGetSymbolAddress(&p_scores, g_scores);
    void* p_cnt;    cudaGetSymbolAddress(&p_cnt, g_cnt);
    cudaMemsetAsync(p_scores, 0, sizeof(float) * Bq * Sq);
    cudaMemsetAsync(p_cnt,    0, sizeof(int) * Bq);
    cudaMemsetAsync(d_out,    0, sizeof(float) * (size_t)out_size);

    maskdetect_kernel<<<1, 256>>>(mask);
    compact_kernel<<<Bq, 256>>>(mask);
    splitw_kernel<<<(HDq * HEq + 255) / 256, 256>>>(W);
    decproj_kernel<<<(Bq * HDq * 32 + 255) / 256, 256>>>(dec, W);
    convertA_kernel<<<dim3(Bq, 16), 256>>>(enc);

    cudaFuncSetAttribute(attn_gemm_kernel,
                         cudaFuncAttributeMaxDynamicSharedMemorySize, SMEM_GEMM_BYTES);
    dim3 grid2(HEq / BN, Bq * (Sq / BM));        // (8, 512)
    attn_gemm_kernel<<<grid2, 256, SMEM_GEMM_BYTES>>>(V);

    softmax_kernel<<<Bq, 256>>>(attn);
    ctx_kernel<<<dim3(Bq, 16), 256>>>(enc, attn, ctx);
}